// round 2
// baseline (speedup 1.0000x reference)
#include <cuda_runtime.h>
#include <math.h>
#include <stdint.h>

// Problem constants
#define BB 2
#define SS 512
#define PP 4096
#define TD 512
#define SD 384
#define HH 8
#define HD 64
#define FF 2048
#define NROW_T (BB*SS)   // 1024
#define NROW_S (BB*PP)   // 8192
#define OUT_ELEMS (NROW_T*TD)
#define ATTN_ELEMS (BB*HH*SS*PP)

// ---------------- device scratch ----------------
__device__ float g_tn[NROW_T*TD];
__device__ float g_sn[NROW_S*SD];
__device__ float g_q[BB*HH*SS*HD];
__device__ float g_k[BB*HH*PP*HD];
__device__ float g_v[BB*HH*PP*HD];
__device__ float g_m[BB*HH*SS];
__device__ float g_z[BB*HH*SS];
__device__ float g_attnout[NROW_T*TD];
__device__ float g_out1[NROW_T*TD];
__device__ float g_hid[NROW_T*FF];
__device__ float g_tmp[NROW_T*TD];
__device__ float g_shead[HH];

// ---------------- fast exp: FFMA/ALU only (MUFU rt=8 on B300 makes expf ~30x slower) ----
__device__ __forceinline__ float fexp(float x) {
    x = fmaxf(x, -87.0f);
    float t = x * 1.44269504088896341f;   // log2(e)
    float r = rintf(t);
    float f = t - r;
    // 2^f, |f| <= 0.5, degree-5 Taylor in ln2 (max rel err ~2.4e-6)
    float p = 1.3333558146e-3f;
    p = fmaf(p, f, 9.6181291076e-3f);
    p = fmaf(p, f, 5.5504108665e-2f);
    p = fmaf(p, f, 2.4022650696e-1f);
    p = fmaf(p, f, 6.9314718056e-1f);
    p = fmaf(p, f, 1.0f);
    int i = (int)r;
    return p * __int_as_float((i + 127) << 23);
}

// ---------------- LayerNorm (optionally fused residual add) ----------------
__global__ void ln_kernel(const float* __restrict__ x, const float* __restrict__ add,
                          const float* __restrict__ g, const float* __restrict__ b,
                          float* __restrict__ y, int D) {
    int row = blockIdx.x;
    const float* xr = x + (size_t)row * D;
    const float* ar = add ? add + (size_t)row * D : nullptr;
    float* yr = y + (size_t)row * D;

    float s = 0.f, ss = 0.f;
    for (int i = threadIdx.x; i < D; i += blockDim.x) {
        float v = xr[i] + (ar ? ar[i] : 0.f);
        s += v; ss += v * v;
    }
    __shared__ float sh[66];
    #pragma unroll
    for (int o = 16; o; o >>= 1) {
        s  += __shfl_xor_sync(0xffffffffu, s, o);
        ss += __shfl_xor_sync(0xffffffffu, ss, o);
    }
    int w = threadIdx.x >> 5;
    if ((threadIdx.x & 31) == 0) { sh[w*2] = s; sh[w*2+1] = ss; }
    __syncthreads();
    int nw = blockDim.x >> 5;
    if (threadIdx.x < 32) {
        s  = threadIdx.x < nw ? sh[threadIdx.x*2]   : 0.f;
        ss = threadIdx.x < nw ? sh[threadIdx.x*2+1] : 0.f;
        #pragma unroll
        for (int o = 16; o; o >>= 1) {
            s  += __shfl_xor_sync(0xffffffffu, s, o);
            ss += __shfl_xor_sync(0xffffffffu, ss, o);
        }
        if (threadIdx.x == 0) { sh[64] = s; sh[65] = ss; }
    }
    __syncthreads();
    float mean = sh[64] / (float)D;
    float var  = sh[65] / (float)D - mean * mean;
    float inv  = rsqrtf(var + 1e-5f);
    for (int i = threadIdx.x; i < D; i += blockDim.x) {
        float v = xr[i] + (ar ? ar[i] : 0.f);
        yr[i] = (v - mean) * inv * g[i] + b[i];
    }
}

// ---------------- per-head edge scalar ----------------
__global__ void edge_scalar_kernel(const float* __restrict__ emb, const float* __restrict__ w,
                                   float* __restrict__ s) {
    int h = threadIdx.x;
    if (h < HH) {
        float acc = 0.f;
        #pragma unroll
        for (int e = 0; e < 32; e++) acc += emb[h*32 + e] * w[e];
        s[h] = acc;
    }
}

// ============ 128x128x8 double-buffered SGEMM (256 thr, 8x8/thread) ============
// MODE 0: plain  MODE 1: head-scatter [b,h,t,d]  MODE 2: exact GELU
template<int MODE>
__global__ __launch_bounds__(256) void sgemm128(
        const float* __restrict__ A, const float* __restrict__ W,
        const float* __restrict__ bias, float* __restrict__ C,
        int M, int N, int K, int T) {
    __shared__ float As[2][8][132];
    __shared__ float Bs[2][8][128];
    int tid = threadIdx.x;
    int tx = tid & 15, ty = tid >> 4;
    int m0 = blockIdx.y * 128, n0 = blockIdx.x * 128;

    int arow = tid >> 1, ak = (tid & 1) * 4;
    int brow = tid >> 5, bcol = (tid & 31) * 4;
    const float* Ap = A + (size_t)(m0 + arow) * K + ak;
    const float* Bp = W + (size_t)brow * N + n0 + bcol;

    float4 aR = *(const float4*)(Ap);
    float4 bR = *(const float4*)(Bp);
    As[0][ak+0][arow]=aR.x; As[0][ak+1][arow]=aR.y; As[0][ak+2][arow]=aR.z; As[0][ak+3][arow]=aR.w;
    *(float4*)(&Bs[0][brow][bcol]) = bR;
    __syncthreads();

    float acc[8][8] = {};
    int buf = 0;
    for (int k0 = 8; k0 <= K; k0 += 8) {
        bool more = k0 < K;
        if (more) {
            aR = *(const float4*)(Ap + k0);
            bR = *(const float4*)(Bp + (size_t)k0 * N);
        }
        #pragma unroll
        for (int kk = 0; kk < 8; kk++) {
            float av[8], bv[8];
            *(float4*)(av)   = *(const float4*)(&As[buf][kk][ty*4]);
            *(float4*)(av+4) = *(const float4*)(&As[buf][kk][ty*4+64]);
            *(float4*)(bv)   = *(const float4*)(&Bs[buf][kk][tx*4]);
            *(float4*)(bv+4) = *(const float4*)(&Bs[buf][kk][tx*4+64]);
            #pragma unroll
            for (int r = 0; r < 8; r++)
                #pragma unroll
                for (int c = 0; c < 8; c++)
                    acc[r][c] = fmaf(av[r], bv[c], acc[r][c]);
        }
        if (more) {
            buf ^= 1;
            As[buf][ak+0][arow]=aR.x; As[buf][ak+1][arow]=aR.y;
            As[buf][ak+2][arow]=aR.z; As[buf][ak+3][arow]=aR.w;
            *(float4*)(&Bs[buf][brow][bcol]) = bR;
            __syncthreads();
        }
    }

    float bz[8];
    *(float4*)(bz)   = *(const float4*)(bias + n0 + tx*4);
    *(float4*)(bz+4) = *(const float4*)(bias + n0 + tx*4 + 64);
    #pragma unroll
    for (int r = 0; r < 8; r++) {
        int row = m0 + ty*4 + (r < 4 ? r : 60 + r);
        #pragma unroll
        for (int half = 0; half < 2; half++) {
            int cb = half*4;
            if ((r < 4) != (cb == 0)) {} // no-op, keep structure simple
            float vals[4];
            #pragma unroll
            for (int c = 0; c < 4; c++) {
                float v = acc[r][cb+c] + bz[cb+c];
                if (MODE == 2) v = 0.5f * v * (1.f + erff(v * 0.70710678118654752f));
                vals[c] = v;
            }
            int col = n0 + tx*4 + half*64;
            float4 o = make_float4(vals[0], vals[1], vals[2], vals[3]);
            if (MODE == 1) {
                int bidx = row / T, t = row % T;
                int h = col >> 6, d = col & 63;
                *(float4*)(C + (size_t)((bidx*HH + h)*T + t)*HD + d) = o;
            } else {
                *(float4*)(C + (size_t)row * N + col) = o;
            }
        }
    }
}

// ============ 64x64x16 double-buffered SGEMM (128 thr, 4x8/thread) for M=1024 GEMMs ====
template<int MODE>
__global__ __launch_bounds__(128) void sgemm64b(
        const float* __restrict__ A, const float* __restrict__ W,
        const float* __restrict__ bias, float* __restrict__ C,
        int M, int N, int K, int T) {
    __shared__ float As[2][16][68];
    __shared__ float Bs[2][16][64];
    int tid = threadIdx.x;
    int tx = tid & 7;        // n frag: tx*4 and tx*4+32
    int ty = tid >> 3;       // m frag: ty*4..+3
    int m0 = blockIdx.y * 64, n0 = blockIdx.x * 64;

    int arow = tid >> 1, ak = (tid & 1) * 8;
    int brow = tid >> 3, bcol = (tid & 7) * 8;
    const float* Ap = A + (size_t)(m0 + arow) * K + ak;
    const float* Bp = W + (size_t)brow * N + n0 + bcol;

    float4 a0 = *(const float4*)(Ap);
    float4 a1 = *(const float4*)(Ap + 4);
    float4 b0 = *(const float4*)(Bp);
    float4 b1 = *(const float4*)(Bp + 4);
    As[0][ak+0][arow]=a0.x; As[0][ak+1][arow]=a0.y; As[0][ak+2][arow]=a0.z; As[0][ak+3][arow]=a0.w;
    As[0][ak+4][arow]=a1.x; As[0][ak+5][arow]=a1.y; As[0][ak+6][arow]=a1.z; As[0][ak+7][arow]=a1.w;
    *(float4*)(&Bs[0][brow][bcol])   = b0;
    *(float4*)(&Bs[0][brow][bcol+4]) = b1;
    __syncthreads();

    float acc[4][8] = {};
    int buf = 0;
    for (int k0 = 16; k0 <= K; k0 += 16) {
        bool more = k0 < K;
        if (more) {
            a0 = *(const float4*)(Ap + k0);
            a1 = *(const float4*)(Ap + k0 + 4);
            b0 = *(const float4*)(Bp + (size_t)k0 * N);
            b1 = *(const float4*)(Bp + (size_t)k0 * N + 4);
        }
        #pragma unroll
        for (int kk = 0; kk < 16; kk++) {
            float av[4], bv[8];
            *(float4*)(av)   = *(const float4*)(&As[buf][kk][ty*4]);
            *(float4*)(bv)   = *(const float4*)(&Bs[buf][kk][tx*4]);
            *(float4*)(bv+4) = *(const float4*)(&Bs[buf][kk][tx*4+32]);
            #pragma unroll
            for (int r = 0; r < 4; r++)
                #pragma unroll
                for (int c = 0; c < 8; c++)
                    acc[r][c] = fmaf(av[r], bv[c], acc[r][c]);
        }
        if (more) {
            buf ^= 1;
            As[buf][ak+0][arow]=a0.x; As[buf][ak+1][arow]=a0.y; As[buf][ak+2][arow]=a0.z; As[buf][ak+3][arow]=a0.w;
            As[buf][ak+4][arow]=a1.x; As[buf][ak+5][arow]=a1.y; As[buf][ak+6][arow]=a1.z; As[buf][ak+7][arow]=a1.w;
            *(float4*)(&Bs[buf][brow][bcol])   = b0;
            *(float4*)(&Bs[buf][brow][bcol+4]) = b1;
            __syncthreads();
        }
    }

    float bz[8];
    *(float4*)(bz)   = *(const float4*)(bias + n0 + tx*4);
    *(float4*)(bz+4) = *(const float4*)(bias + n0 + tx*4 + 32);
    #pragma unroll
    for (int r = 0; r < 4; r++) {
        int row = m0 + ty*4 + r;
        #pragma unroll
        for (int half = 0; half < 2; half++) {
            float vals[4];
            #pragma unroll
            for (int c = 0; c < 4; c++) {
                float v = acc[r][half*4+c] + bz[half*4+c];
                if (MODE == 2) v = 0.5f * v * (1.f + erff(v * 0.70710678118654752f));
                vals[c] = v;
            }
            int col = n0 + tx*4 + half*32;
            float4 o = make_float4(vals[0], vals[1], vals[2], vals[3]);
            if (MODE == 1) {
                int bidx = row / T, t = row % T;
                int h = col >> 6, d = col & 63;
                *(float4*)(C + (size_t)((bidx*HH + h)*T + t)*HD + d) = o;
            } else {
                *(float4*)(C + (size_t)row * N + col) = o;
            }
        }
    }
}

// ---------------- attention pass A: logits + running (m, Z) in registers ----------------
// grid: (S/64, B*H), 256 threads, i-tile 64 x j-tile 128, 4x8 acc/thread.
__global__ __launch_bounds__(256) void attn_scores_kernel(
        const float* __restrict__ q, const float* __restrict__ k,
        const float* __restrict__ shead, const float* __restrict__ ep_b,
        float* __restrict__ logits, float* __restrict__ gm, float* __restrict__ gz) {
    __shared__ float qs[64][64];   // qs[d][i]
    __shared__ float ks[64][128];  // ks[d][j]
    int tid = threadIdx.x;
    int tx = tid & 15, ty = tid >> 4;
    int bh = blockIdx.y;
    int i0 = blockIdx.x * 64;
    const float* qb = q + ((size_t)bh * SS + i0) * HD;
    const float* kb = k + (size_t)bh * PP * HD;
    float* lb = logits + ((size_t)bh * SS + i0) * PP;
    float sh_scale = shead[bh & (HH-1)];
    float epb = ep_b[0];

    // q tile -> qs[d][i] (once per block)
    {
        int i = tid >> 2;
        int dbase = (tid & 3) * 4;
        #pragma unroll
        for (int dd = 0; dd < 4; dd++) {
            int d4 = dbase + dd*16;
            float4 v = *(const float4*)(qb + (size_t)i*HD + d4);
            qs[d4+0][i]=v.x; qs[d4+1][i]=v.y; qs[d4+2][i]=v.z; qs[d4+3][i]=v.w;
        }
    }
    float m_run[4], l_run[4];
    #pragma unroll
    for (int r = 0; r < 4; r++) { m_run[r] = -1e30f; l_run[r] = 0.f; }

    int kj = tid >> 1;
    int kd = (tid & 1) * 4;
    for (int j0 = 0; j0 < PP; j0 += 128) {
        __syncthreads();
        #pragma unroll
        for (int dd = 0; dd < 8; dd++) {
            int d4 = kd + dd*8;
            float4 v = *(const float4*)(kb + (size_t)(j0 + kj)*HD + d4);
            ks[d4+0][kj]=v.x; ks[d4+1][kj]=v.y; ks[d4+2][kj]=v.z; ks[d4+3][kj]=v.w;
        }
        __syncthreads();

        float acc[4][8] = {};
        #pragma unroll 8
        for (int d = 0; d < 64; d++) {
            float av[4], bv[8];
            *(float4*)(av)   = *(const float4*)(&qs[d][ty*4]);
            *(float4*)(bv)   = *(const float4*)(&ks[d][tx*4]);
            *(float4*)(bv+4) = *(const float4*)(&ks[d][tx*4+64]);
            #pragma unroll
            for (int r = 0; r < 4; r++)
                #pragma unroll
                for (int c = 0; c < 8; c++)
                    acc[r][c] = fmaf(av[r], bv[c], acc[r][c]);
        }

        #pragma unroll
        for (int r = 0; r < 4; r++) {
            float vrow[8];
            #pragma unroll
            for (int c = 0; c < 8; c++) {
                float sc = acc[r][c] * 0.125f;
                float t = fmaf(sc, sh_scale, epb);
                float e = t > 0.f ? t : 0.2f * t;
                vrow[c] = sc + e;
            }
            int iloc = ty*4 + r;
            *(float4*)(lb + (size_t)iloc*PP + j0 + tx*4) =
                make_float4(vrow[0], vrow[1], vrow[2], vrow[3]);
            *(float4*)(lb + (size_t)iloc*PP + j0 + tx*4 + 64) =
                make_float4(vrow[4], vrow[5], vrow[6], vrow[7]);

            float tm = vrow[0];
            #pragma unroll
            for (int c = 1; c < 8; c++) tm = fmaxf(tm, vrow[c]);
            #pragma unroll
            for (int o = 8; o; o >>= 1) tm = fmaxf(tm, __shfl_xor_sync(0xffffffffu, tm, o));
            float nm = fmaxf(m_run[r], tm);
            float pe = 0.f;
            #pragma unroll
            for (int c = 0; c < 8; c++) pe += fexp(vrow[c] - nm);
            #pragma unroll
            for (int o = 8; o; o >>= 1) pe += __shfl_xor_sync(0xffffffffu, pe, o);
            l_run[r] = l_run[r] * fexp(m_run[r] - nm) + pe;
            m_run[r] = nm;
        }
    }

    if (tx == 0) {
        #pragma unroll
        for (int r = 0; r < 4; r++) {
            gm[(size_t)bh*SS + i0 + ty*4 + r] = m_run[r];
            gz[(size_t)bh*SS + i0 + ty*4 + r] = l_run[r];
        }
    }
}

// ---------------- attention pass B: normalize attn in place + P @ V ----------------
__global__ __launch_bounds__(256) void attn_pv_kernel(
        const float* __restrict__ v,
        const float* __restrict__ gm, const float* __restrict__ gz,
        float* __restrict__ attn, float* __restrict__ out) {
    __shared__ float ps[64*68];
    __shared__ float vs[64*68];
    __shared__ float sm_m[64], sm_iz[64];
    int tid = threadIdx.x;
    int tx = tid & 15, ty = tid >> 4;
    int bh = blockIdx.y;
    int b = bh >> 3, h = bh & 7;
    int i0 = blockIdx.x * 64;
    float* ab = attn + ((size_t)bh * SS + i0) * PP;
    const float* vb = v + (size_t)bh * PP * HD;

    if (tid < 64) {
        sm_m[tid]  = gm[(size_t)bh*SS + i0 + tid];
        sm_iz[tid] = 1.f / gz[(size_t)bh*SS + i0 + tid];
    }
    __syncthreads();

    float acc[4][4] = {};
    for (int j0 = 0; j0 < PP; j0 += 64) {
        #pragma unroll
        for (int rr = 0; rr < 4; rr++) {
            int i = (tid >> 4) + rr*16;
            int j4 = (tid & 15) * 4;
            float4 lv = *(const float4*)(ab + (size_t)i*PP + j0 + j4);
            float m = sm_m[i], iz = sm_iz[i];
            float p0 = fexp(lv.x - m) * iz;
            float p1 = fexp(lv.y - m) * iz;
            float p2 = fexp(lv.z - m) * iz;
            float p3 = fexp(lv.w - m) * iz;
            *(float4*)(ab + (size_t)i*PP + j0 + j4) = make_float4(p0, p1, p2, p3);
            ps[(j4+0)*68 + i] = p0;
            ps[(j4+1)*68 + i] = p1;
            ps[(j4+2)*68 + i] = p2;
            ps[(j4+3)*68 + i] = p3;
            int j = i, d4 = j4;
            *(float4*)(vs + j*68 + d4) = *(const float4*)(vb + (size_t)(j0 + j)*HD + d4);
        }
        __syncthreads();
        #pragma unroll 16
        for (int jj = 0; jj < 64; jj++) {
            float4 av = *(const float4*)(ps + jj*68 + ty*4);
            float4 bv = *(const float4*)(vs + jj*68 + tx*4);
            float ax[4] = {av.x, av.y, av.z, av.w};
            float bx[4] = {bv.x, bv.y, bv.z, bv.w};
            #pragma unroll
            for (int r = 0; r < 4; r++)
                #pragma unroll
                for (int c = 0; c < 4; c++)
                    acc[r][c] = fmaf(ax[r], bx[c], acc[r][c]);
        }
        __syncthreads();
    }

    #pragma unroll
    for (int r = 0; r < 4; r++) {
        int row = (b*SS + i0 + ty*4 + r);
        *(float4*)(out + (size_t)row*TD + h*HD + tx*4) =
            make_float4(acc[r][0], acc[r][1], acc[r][2], acc[r][3]);
    }
}

// ---------------- launch ----------------
extern "C" void kernel_launch(void* const* d_in, const int* in_sizes, int n_in,
                              void* d_out, int out_size) {
    const float* text  = (const float*)d_in[0];
    const float* shape = (const float*)d_in[1];
    const float* tn_g = (const float*)d_in[2];
    const float* tn_b = (const float*)d_in[3];
    const float* sn_g = (const float*)d_in[4];
    const float* sn_b = (const float*)d_in[5];
    const float* Wq = (const float*)d_in[6];
    const float* bq = (const float*)d_in[7];
    const float* Wk = (const float*)d_in[8];
    const float* bk = (const float*)d_in[9];
    const float* Wv = (const float*)d_in[10];
    const float* bv = (const float*)d_in[11];
    const float* edge_emb = (const float*)d_in[12];
    const float* ep_w = (const float*)d_in[13];
    const float* ep_b = (const float*)d_in[14];
    const float* Wo = (const float*)d_in[15];
    const float* bo = (const float*)d_in[16];
    const float* on_g = (const float*)d_in[17];
    const float* on_b = (const float*)d_in[18];
    const float* W1 = (const float*)d_in[19];
    const float* b1 = (const float*)d_in[20];
    const float* W2 = (const float*)d_in[21];
    const float* b2 = (const float*)d_in[22];
    const float* fn_g = (const float*)d_in[23];
    const float* fn_b = (const float*)d_in[24];

    float* out_final = (float*)d_out;
    float* attn_buf  = (float*)d_out + OUT_ELEMS;

    float *p_tn, *p_sn, *p_q, *p_k, *p_v, *p_m, *p_z, *p_ao, *p_o1, *p_hid, *p_tmp, *p_sh;
    cudaGetSymbolAddress((void**)&p_tn, g_tn);
    cudaGetSymbolAddress((void**)&p_sn, g_sn);
    cudaGetSymbolAddress((void**)&p_q,  g_q);
    cudaGetSymbolAddress((void**)&p_k,  g_k);
    cudaGetSymbolAddress((void**)&p_v,  g_v);
    cudaGetSymbolAddress((void**)&p_m,  g_m);
    cudaGetSymbolAddress((void**)&p_z,  g_z);
    cudaGetSymbolAddress((void**)&p_ao, g_attnout);
    cudaGetSymbolAddress((void**)&p_o1, g_out1);
    cudaGetSymbolAddress((void**)&p_hid, g_hid);
    cudaGetSymbolAddress((void**)&p_tmp, g_tmp);
    cudaGetSymbolAddress((void**)&p_sh, g_shead);

    // 1. input LayerNorms + edge scalar
    ln_kernel<<<NROW_T, 128>>>(text, nullptr, tn_g, tn_b, p_tn, TD);
    ln_kernel<<<NROW_S, 128>>>(shape, nullptr, sn_g, sn_b, p_sn, SD);
    edge_scalar_kernel<<<1, 32>>>(edge_emb, ep_w, p_sh);

    // 2. projections
    sgemm64b<1><<<dim3(TD/64, NROW_T/64), 128>>>(p_tn, Wq, bq, p_q, NROW_T, TD, TD, SS);
    sgemm128<1><<<dim3(TD/128, NROW_S/128), 256>>>(p_sn, Wk, bk, p_k, NROW_S, TD, SD, PP);
    sgemm128<1><<<dim3(TD/128, NROW_S/128), 256>>>(p_sn, Wv, bv, p_v, NROW_S, TD, SD, PP);

    // 3. attention
    attn_scores_kernel<<<dim3(SS/64, BB*HH), 256>>>(p_q, p_k, p_sh, ep_b, attn_buf, p_m, p_z);
    attn_pv_kernel<<<dim3(SS/64, BB*HH), 256>>>(p_v, p_m, p_z, attn_buf, p_ao);

    // 4. output proj + residual + LN
    sgemm64b<0><<<dim3(TD/64, NROW_T/64), 128>>>(p_ao, Wo, bo, p_tmp, NROW_T, TD, TD, 0);
    ln_kernel<<<NROW_T, 128>>>(text, p_tmp, on_g, on_b, p_o1, TD);

    // 5. FFN + residual + LN
    sgemm64b<2><<<dim3(FF/64, NROW_T/64), 128>>>(p_o1, W1, b1, p_hid, NROW_T, FF, TD, 0);
    sgemm64b<0><<<dim3(TD/64, NROW_T/64), 128>>>(p_hid, W2, b2, p_tmp, NROW_T, TD, FF, 0);
    ln_kernel<<<NROW_T, 128>>>(p_o1, p_tmp, fn_g, fn_b, out_final, TD);
}

// round 3
// speedup vs baseline: 1.7225x; 1.7225x over previous
#include <cuda_runtime.h>
#include <cuda_bf16.h>
#include <math.h>
#include <stdint.h>

// Problem constants
#define BB 2
#define SS 512
#define PP 4096
#define TD 512
#define SD 384
#define HH 8
#define HD 64
#define FF 2048
#define NROW_T (BB*SS)   // 1024
#define NROW_S (BB*PP)   // 8192
#define OUT_ELEMS (NROW_T*TD)

// ---------------- device scratch ----------------
__device__ float g_tn[NROW_T*TD];
__device__ float g_sn[NROW_S*SD];
__device__ float g_q[BB*HH*SS*HD];
__device__ float g_k[BB*HH*PP*HD];
__device__ float g_v[BB*HH*PP*HD];
__device__ float g_m[BB*HH*SS];
__device__ float g_z[BB*HH*SS];
__device__ float g_attnout[NROW_T*TD];
__device__ float g_out1[NROW_T*TD];
__device__ float g_hid[NROW_T*FF];
__device__ float g_tmp[NROW_T*TD];
__device__ float g_shead[HH];

// ---------------- fast exp: FFMA/ALU only ----------------
__device__ __forceinline__ float fexp(float x) {
    x = fmaxf(x, -87.0f);
    float t = x * 1.44269504088896341f;
    float r = rintf(t);
    float f = t - r;
    float p = 1.3333558146e-3f;
    p = fmaf(p, f, 9.6181291076e-3f);
    p = fmaf(p, f, 5.5504108665e-2f);
    p = fmaf(p, f, 2.4022650696e-1f);
    p = fmaf(p, f, 6.9314718056e-1f);
    p = fmaf(p, f, 1.0f);
    int i = (int)r;
    return p * __int_as_float((i + 127) << 23);
}

// ---------------- LayerNorm ----------------
__global__ void ln_kernel(const float* __restrict__ x, const float* __restrict__ add,
                          const float* __restrict__ g, const float* __restrict__ b,
                          float* __restrict__ y, int D) {
    int row = blockIdx.x;
    const float* xr = x + (size_t)row * D;
    const float* ar = add ? add + (size_t)row * D : nullptr;
    float* yr = y + (size_t)row * D;

    float s = 0.f, ss = 0.f;
    for (int i = threadIdx.x; i < D; i += blockDim.x) {
        float v = xr[i] + (ar ? ar[i] : 0.f);
        s += v; ss += v * v;
    }
    __shared__ float sh[66];
    #pragma unroll
    for (int o = 16; o; o >>= 1) {
        s  += __shfl_xor_sync(0xffffffffu, s, o);
        ss += __shfl_xor_sync(0xffffffffu, ss, o);
    }
    int w = threadIdx.x >> 5;
    if ((threadIdx.x & 31) == 0) { sh[w*2] = s; sh[w*2+1] = ss; }
    __syncthreads();
    int nw = blockDim.x >> 5;
    if (threadIdx.x < 32) {
        s  = threadIdx.x < nw ? sh[threadIdx.x*2]   : 0.f;
        ss = threadIdx.x < nw ? sh[threadIdx.x*2+1] : 0.f;
        #pragma unroll
        for (int o = 16; o; o >>= 1) {
            s  += __shfl_xor_sync(0xffffffffu, s, o);
            ss += __shfl_xor_sync(0xffffffffu, ss, o);
        }
        if (threadIdx.x == 0) { sh[64] = s; sh[65] = ss; }
    }
    __syncthreads();
    float mean = sh[64] / (float)D;
    float var  = sh[65] / (float)D - mean * mean;
    float inv  = rsqrtf(var + 1e-5f);
    for (int i = threadIdx.x; i < D; i += blockDim.x) {
        float v = xr[i] + (ar ? ar[i] : 0.f);
        yr[i] = (v - mean) * inv * g[i] + b[i];
    }
}

__global__ void edge_scalar_kernel(const float* __restrict__ emb, const float* __restrict__ w,
                                   float* __restrict__ s) {
    int h = threadIdx.x;
    if (h < HH) {
        float acc = 0.f;
        #pragma unroll
        for (int e = 0; e < 32; e++) acc += emb[h*32 + e] * w[e];
        s[h] = acc;
    }
}

// ================== bf16 split-precision tensor-core GEMM ==================
__device__ __forceinline__ void ldsm4(uint32_t& r0, uint32_t& r1, uint32_t& r2, uint32_t& r3,
                                      uint32_t addr) {
    asm volatile("ldmatrix.sync.aligned.m8n8.x4.shared.b16 {%0,%1,%2,%3}, [%4];"
        : "=r"(r0), "=r"(r1), "=r"(r2), "=r"(r3) : "r"(addr));
}
__device__ __forceinline__ void ldsm4t(uint32_t& r0, uint32_t& r1, uint32_t& r2, uint32_t& r3,
                                       uint32_t addr) {
    asm volatile("ldmatrix.sync.aligned.m8n8.x4.trans.shared.b16 {%0,%1,%2,%3}, [%4];"
        : "=r"(r0), "=r"(r1), "=r"(r2), "=r"(r3) : "r"(addr));
}
__device__ __forceinline__ void mma16816(float* c, const uint32_t* a, uint32_t b0, uint32_t b1) {
    asm volatile(
        "mma.sync.aligned.m16n8k16.row.col.f32.bf16.bf16.f32 "
        "{%0,%1,%2,%3},{%4,%5,%6,%7},{%8,%9},{%0,%1,%2,%3};"
        : "+f"(c[0]), "+f"(c[1]), "+f"(c[2]), "+f"(c[3])
        : "r"(a[0]), "r"(a[1]), "r"(a[2]), "r"(a[3]), "r"(b0), "r"(b1));
}
__device__ __forceinline__ uint32_t pack2(unsigned short a, unsigned short b) {
    return (uint32_t)a | ((uint32_t)b << 16);
}
// split 4 floats -> 4 bf16 hi (2 u32) + 4 bf16 lo (2 u32)
__device__ __forceinline__ void split4(float x0, float x1, float x2, float x3,
                                       uint32_t* hi, uint32_t* lo) {
    __nv_bfloat16 h0 = __float2bfloat16(x0);
    __nv_bfloat16 h1 = __float2bfloat16(x1);
    __nv_bfloat16 h2 = __float2bfloat16(x2);
    __nv_bfloat16 h3 = __float2bfloat16(x3);
    __nv_bfloat16 l0 = __float2bfloat16(x0 - __bfloat162float(h0));
    __nv_bfloat16 l1 = __float2bfloat16(x1 - __bfloat162float(h1));
    __nv_bfloat16 l2 = __float2bfloat16(x2 - __bfloat162float(h2));
    __nv_bfloat16 l3 = __float2bfloat16(x3 - __bfloat162float(h3));
    hi[0] = pack2(__bfloat16_as_ushort(h0), __bfloat16_as_ushort(h1));
    hi[1] = pack2(__bfloat16_as_ushort(h2), __bfloat16_as_ushort(h3));
    lo[0] = pack2(__bfloat16_as_ushort(l0), __bfloat16_as_ushort(l1));
    lo[1] = pack2(__bfloat16_as_ushort(l2), __bfloat16_as_ushort(l3));
}

// C[M,N] = A[M,K] @ W[K,N] + bias, fp32 in/out, bf16-split x3 mma internally.
// MODE 0: plain  MODE 1: head-scatter [b,h,t,d] (T tokens/batch)  MODE 2: exact GELU
template<int BM, int BN, int NWM, int NWN, int MODE>
__global__ __launch_bounds__(32*NWM*NWN) void mma_gemm(
        const float* __restrict__ A, const float* __restrict__ W,
        const float* __restrict__ bias, float* __restrict__ C,
        int M, int N, int K, int T) {
    constexpr int WM = BM / NWM;          // 32
    constexpr int WN = BN / NWN;          // 64 or 32
    constexpr int MT = WM / 16;           // 2
    constexpr int NT = WN / 8;            // 8 or 4
    constexpr int SA = 40;                // bf16 units per A row (80B)
    constexpr int SB = BN + 8;            // bf16 units per B row

    __shared__ uint16_t As[2][BM * SA];   // [hi/lo][row*SA + k]
    __shared__ uint16_t Bs[2][32 * SB];   // [hi/lo][k*SB + n]

    int tid = threadIdx.x;
    int l = tid & 31, w = tid >> 5;
    int wm = w / NWN, wn = w % NWN;
    int m0 = blockIdx.y * BM, n0 = blockIdx.x * BN;

    // global->smem assignments
    int arow = tid >> 1, akseg = (tid & 1) * 16;           // NTH == 2*BM
    int bk = tid / (BN / 16), bn = (tid % (BN / 16)) * 16; // NTH == 32*(BN/16)

    // fragment smem byte addresses (ks=0)
    uint32_t aBaseHi = (uint32_t)__cvta_generic_to_shared(&As[0][0]);
    uint32_t aBaseLo = (uint32_t)__cvta_generic_to_shared(&As[1][0]);
    uint32_t bBaseHi = (uint32_t)__cvta_generic_to_shared(&Bs[0][0]);
    uint32_t bBaseLo = (uint32_t)__cvta_generic_to_shared(&Bs[1][0]);

    uint32_t aAddr[MT];
    #pragma unroll
    for (int mt = 0; mt < MT; mt++) {
        int row = wm * WM + mt * 16 + (l & 15);
        int koff = (l >> 4) * 8;
        aAddr[mt] = (uint32_t)((row * SA + koff) * 2);
    }
    uint32_t bAddr[NT / 2];
    #pragma unroll
    for (int p = 0; p < NT / 2; p++) {
        int kk = (l & 7) + ((l >> 3) & 1) * 8;
        int nn = wn * WN + p * 16 + (l >> 4) * 8;
        bAddr[p] = (uint32_t)((kk * SB + nn) * 2);
    }

    float acc[MT][NT][4];
    #pragma unroll
    for (int mt = 0; mt < MT; mt++)
        #pragma unroll
        for (int nt = 0; nt < NT; nt++)
            #pragma unroll
            for (int i = 0; i < 4; i++) acc[mt][nt][i] = 0.f;

    for (int k0 = 0; k0 < K; k0 += 32) {
        __syncthreads();
        // ---- A chunk: BM x 32 ----
        {
            const float* Ag = A + (size_t)(m0 + arow) * K + k0 + akseg;
            float4 f0 = *(const float4*)(Ag);
            float4 f1 = *(const float4*)(Ag + 4);
            float4 f2 = *(const float4*)(Ag + 8);
            float4 f3 = *(const float4*)(Ag + 12);
            uint4 hi0, lo0, hi1, lo1;
            split4(f0.x, f0.y, f0.z, f0.w, &hi0.x, &lo0.x);
            split4(f1.x, f1.y, f1.z, f1.w, &hi0.z, &lo0.z);
            split4(f2.x, f2.y, f2.z, f2.w, &hi1.x, &lo1.x);
            split4(f3.x, f3.y, f3.z, f3.w, &hi1.z, &lo1.z);
            int idx = arow * SA + akseg;
            *(uint4*)(&As[0][idx])     = hi0;
            *(uint4*)(&As[0][idx + 8]) = hi1;
            *(uint4*)(&As[1][idx])     = lo0;
            *(uint4*)(&As[1][idx + 8]) = lo1;
        }
        // ---- B chunk: 32 x BN ----
        {
            const float* Wg = W + (size_t)(k0 + bk) * N + n0 + bn;
            float4 f0 = *(const float4*)(Wg);
            float4 f1 = *(const float4*)(Wg + 4);
            float4 f2 = *(const float4*)(Wg + 8);
            float4 f3 = *(const float4*)(Wg + 12);
            uint4 hi0, lo0, hi1, lo1;
            split4(f0.x, f0.y, f0.z, f0.w, &hi0.x, &lo0.x);
            split4(f1.x, f1.y, f1.z, f1.w, &hi0.z, &lo0.z);
            split4(f2.x, f2.y, f2.z, f2.w, &hi1.x, &lo1.x);
            split4(f3.x, f3.y, f3.z, f3.w, &hi1.z, &lo1.z);
            int idx = bk * SB + bn;
            *(uint4*)(&Bs[0][idx])     = hi0;
            *(uint4*)(&Bs[0][idx + 8]) = hi1;
            *(uint4*)(&Bs[1][idx])     = lo0;
            *(uint4*)(&Bs[1][idx + 8]) = lo1;
        }
        __syncthreads();

        #pragma unroll
        for (int ks = 0; ks < 32; ks += 16) {
            uint32_t aHi[MT][4], aLo[MT][4];
            #pragma unroll
            for (int mt = 0; mt < MT; mt++) {
                ldsm4(aHi[mt][0], aHi[mt][1], aHi[mt][2], aHi[mt][3],
                      aBaseHi + aAddr[mt] + ks * 2);
                ldsm4(aLo[mt][0], aLo[mt][1], aLo[mt][2], aLo[mt][3],
                      aBaseLo + aAddr[mt] + ks * 2);
            }
            #pragma unroll
            for (int p = 0; p < NT / 2; p++) {
                uint32_t bh[4], bl[4];
                ldsm4t(bh[0], bh[1], bh[2], bh[3], bBaseHi + bAddr[p] + ks * SB * 2);
                ldsm4t(bl[0], bl[1], bl[2], bl[3], bBaseLo + bAddr[p] + ks * SB * 2);
                #pragma unroll
                for (int q = 0; q < 2; q++) {
                    int nt = 2 * p + q;
                    #pragma unroll
                    for (int mt = 0; mt < MT; mt++) {
                        mma16816(acc[mt][nt], aHi[mt], bh[2*q], bh[2*q+1]); // hi*hi
                        mma16816(acc[mt][nt], aHi[mt], bl[2*q], bl[2*q+1]); // hi*lo
                        mma16816(acc[mt][nt], aLo[mt], bh[2*q], bh[2*q+1]); // lo*hi
                    }
                }
            }
        }
    }

    // ---- epilogue ----
    #pragma unroll
    for (int mt = 0; mt < MT; mt++) {
        int row0 = m0 + wm * WM + mt * 16 + (l >> 2);
        #pragma unroll
        for (int nt = 0; nt < NT; nt++) {
            int col = n0 + wn * WN + nt * 8 + (l & 3) * 2;
            float b0 = bias[col], b1 = bias[col + 1];
            float v00 = acc[mt][nt][0] + b0, v01 = acc[mt][nt][1] + b1;
            float v10 = acc[mt][nt][2] + b0, v11 = acc[mt][nt][3] + b1;
            if (MODE == 2) {
                v00 = 0.5f * v00 * (1.f + erff(v00 * 0.70710678118654752f));
                v01 = 0.5f * v01 * (1.f + erff(v01 * 0.70710678118654752f));
                v10 = 0.5f * v10 * (1.f + erff(v10 * 0.70710678118654752f));
                v11 = 0.5f * v11 * (1.f + erff(v11 * 0.70710678118654752f));
            }
            if (MODE == 1) {
                int h = col >> 6, d = col & 63;
                int bi0 = row0 / T, t0 = row0 % T;
                int bi1 = (row0 + 8) / T, t1 = (row0 + 8) % T;
                *(float2*)(C + (size_t)((bi0*HH + h)*T + t0)*HD + d) = make_float2(v00, v01);
                *(float2*)(C + (size_t)((bi1*HH + h)*T + t1)*HD + d) = make_float2(v10, v11);
            } else {
                *(float2*)(C + (size_t)row0 * N + col)       = make_float2(v00, v01);
                *(float2*)(C + (size_t)(row0 + 8) * N + col) = make_float2(v10, v11);
            }
        }
    }
}

// ---------------- attention pass A: i-tile 32, j-tile 64, fexp stats ----------------
// grid (SS/32, BB*HH), 256 threads
__global__ __launch_bounds__(256) void attn_scores_kernel(
        const float* __restrict__ q, const float* __restrict__ k,
        const float* __restrict__ shead, const float* __restrict__ ep_b,
        float* __restrict__ logits, float* __restrict__ gm, float* __restrict__ gz) {
    __shared__ float qs[64][36];   // [d][i], i<32
    __shared__ float ks[64][68];   // [d][j], j<64
    int tid = threadIdx.x;
    int tx = tid & 15, ty = tid >> 4;     // ty 0..15 -> rows ty*2, ty*2+1
    int bh = blockIdx.y;
    int i0 = blockIdx.x * 32;
    const float* qb = q + ((size_t)bh * SS + i0) * HD;
    const float* kb = k + (size_t)bh * PP * HD;
    float* lb = logits + ((size_t)bh * SS + i0) * PP;
    float sh_scale = shead[bh & (HH-1)];
    float epb = ep_b[0];

    // q tile -> qs[d][i]
    {
        int i = tid >> 3;             // 32 rows, 8 thr/row
        int dbase = (tid & 7) * 8;
        float4 v0 = *(const float4*)(qb + (size_t)i*HD + dbase);
        float4 v1 = *(const float4*)(qb + (size_t)i*HD + dbase + 4);
        qs[dbase+0][i]=v0.x; qs[dbase+1][i]=v0.y; qs[dbase+2][i]=v0.z; qs[dbase+3][i]=v0.w;
        qs[dbase+4][i]=v1.x; qs[dbase+5][i]=v1.y; qs[dbase+6][i]=v1.z; qs[dbase+7][i]=v1.w;
    }
    float m_run[2] = {-1e30f, -1e30f};
    float l_run[2] = {0.f, 0.f};

    int kj = tid >> 2;            // 64 rows, 4 thr/row
    int kd = (tid & 3) * 16;
    for (int j0 = 0; j0 < PP; j0 += 64) {
        __syncthreads();
        #pragma unroll
        for (int t = 0; t < 4; t++) {
            float4 v = *(const float4*)(kb + (size_t)(j0 + kj)*HD + kd + t*4);
            ks[kd+t*4+0][kj]=v.x; ks[kd+t*4+1][kj]=v.y; ks[kd+t*4+2][kj]=v.z; ks[kd+t*4+3][kj]=v.w;
        }
        __syncthreads();

        float acc[2][4] = {};
        #pragma unroll 8
        for (int d = 0; d < 64; d++) {
            float2 av = *(const float2*)(&qs[d][ty*2]);
            float4 bv = *(const float4*)(&ks[d][tx*4]);
            float ax[2] = {av.x, av.y};
            float bx[4] = {bv.x, bv.y, bv.z, bv.w};
            #pragma unroll
            for (int r = 0; r < 2; r++)
                #pragma unroll
                for (int c = 0; c < 4; c++)
                    acc[r][c] = fmaf(ax[r], bx[c], acc[r][c]);
        }

        #pragma unroll
        for (int r = 0; r < 2; r++) {
            float vrow[4];
            #pragma unroll
            for (int c = 0; c < 4; c++) {
                float sc = acc[r][c] * 0.125f;
                float t = fmaf(sc, sh_scale, epb);
                float e = t > 0.f ? t : 0.2f * t;
                vrow[c] = sc + e;
            }
            int iloc = ty*2 + r;
            *(float4*)(lb + (size_t)iloc*PP + j0 + tx*4) =
                make_float4(vrow[0], vrow[1], vrow[2], vrow[3]);

            float tm = fmaxf(fmaxf(vrow[0], vrow[1]), fmaxf(vrow[2], vrow[3]));
            #pragma unroll
            for (int o = 8; o; o >>= 1) tm = fmaxf(tm, __shfl_xor_sync(0xffffffffu, tm, o));
            float nm = fmaxf(m_run[r], tm);
            float pe = fexp(vrow[0]-nm) + fexp(vrow[1]-nm) + fexp(vrow[2]-nm) + fexp(vrow[3]-nm);
            #pragma unroll
            for (int o = 8; o; o >>= 1) pe += __shfl_xor_sync(0xffffffffu, pe, o);
            l_run[r] = l_run[r] * fexp(m_run[r] - nm) + pe;
            m_run[r] = nm;
        }
    }

    if (tx == 0) {
        #pragma unroll
        for (int r = 0; r < 2; r++) {
            gm[(size_t)bh*SS + i0 + ty*2 + r] = m_run[r];
            gz[(size_t)bh*SS + i0 + ty*2 + r] = l_run[r];
        }
    }
}

// ---------------- attention pass B (R1-proven) + fexp ----------------
__global__ __launch_bounds__(256) void attn_pv_kernel(
        const float* __restrict__ v,
        const float* __restrict__ gm, const float* __restrict__ gz,
        float* __restrict__ attn, float* __restrict__ out) {
    __shared__ float ps[64*68];
    __shared__ float vs[64*68];
    __shared__ float sm_m[64], sm_iz[64];
    int tid = threadIdx.x;
    int tx = tid & 15, ty = tid >> 4;
    int bh = blockIdx.y;
    int b = bh >> 3, h = bh & 7;
    int i0 = blockIdx.x * 64;
    float* ab = attn + ((size_t)bh * SS + i0) * PP;
    const float* vb = v + (size_t)bh * PP * HD;

    if (tid < 64) {
        sm_m[tid]  = gm[(size_t)bh*SS + i0 + tid];
        sm_iz[tid] = 1.f / gz[(size_t)bh*SS + i0 + tid];
    }
    __syncthreads();

    float acc[4][4] = {};
    for (int j0 = 0; j0 < PP; j0 += 64) {
        #pragma unroll
        for (int rr = 0; rr < 4; rr++) {
            int i = (tid >> 4) + rr*16;
            int j4 = (tid & 15) * 4;
            float4 lv = *(const float4*)(ab + (size_t)i*PP + j0 + j4);
            float m = sm_m[i], iz = sm_iz[i];
            float p0 = fexp(lv.x - m) * iz;
            float p1 = fexp(lv.y - m) * iz;
            float p2 = fexp(lv.z - m) * iz;
            float p3 = fexp(lv.w - m) * iz;
            *(float4*)(ab + (size_t)i*PP + j0 + j4) = make_float4(p0, p1, p2, p3);
            ps[(j4+0)*68 + i] = p0;
            ps[(j4+1)*68 + i] = p1;
            ps[(j4+2)*68 + i] = p2;
            ps[(j4+3)*68 + i] = p3;
            int j = i, d4 = j4;
            *(float4*)(vs + j*68 + d4) = *(const float4*)(vb + (size_t)(j0 + j)*HD + d4);
        }
        __syncthreads();
        #pragma unroll 16
        for (int jj = 0; jj < 64; jj++) {
            float4 av = *(const float4*)(ps + jj*68 + ty*4);
            float4 bv = *(const float4*)(vs + jj*68 + tx*4);
            float ax[4] = {av.x, av.y, av.z, av.w};
            float bx[4] = {bv.x, bv.y, bv.z, bv.w};
            #pragma unroll
            for (int r = 0; r < 4; r++)
                #pragma unroll
                for (int c = 0; c < 4; c++)
                    acc[r][c] = fmaf(ax[r], bx[c], acc[r][c]);
        }
        __syncthreads();
    }

    #pragma unroll
    for (int r = 0; r < 4; r++) {
        int row = (b*SS + i0 + ty*4 + r);
        *(float4*)(out + (size_t)row*TD + h*HD + tx*4) =
            make_float4(acc[r][0], acc[r][1], acc[r][2], acc[r][3]);
    }
}

// ---------------- launch ----------------
extern "C" void kernel_launch(void* const* d_in, const int* in_sizes, int n_in,
                              void* d_out, int out_size) {
    const float* text  = (const float*)d_in[0];
    const float* shape = (const float*)d_in[1];
    const float* tn_g = (const float*)d_in[2];
    const float* tn_b = (const float*)d_in[3];
    const float* sn_g = (const float*)d_in[4];
    const float* sn_b = (const float*)d_in[5];
    const float* Wq = (const float*)d_in[6];
    const float* bq = (const float*)d_in[7];
    const float* Wk = (const float*)d_in[8];
    const float* bk = (const float*)d_in[9];
    const float* Wv = (const float*)d_in[10];
    const float* bv = (const float*)d_in[11];
    const float* edge_emb = (const float*)d_in[12];
    const float* ep_w = (const float*)d_in[13];
    const float* ep_b = (const float*)d_in[14];
    const float* Wo = (const float*)d_in[15];
    const float* bo = (const float*)d_in[16];
    const float* on_g = (const float*)d_in[17];
    const float* on_b = (const float*)d_in[18];
    const float* W1 = (const float*)d_in[19];
    const float* b1 = (const float*)d_in[20];
    const float* W2 = (const float*)d_in[21];
    const float* b2 = (const float*)d_in[22];
    const float* fn_g = (const float*)d_in[23];
    const float* fn_b = (const float*)d_in[24];

    float* out_final = (float*)d_out;
    float* attn_buf  = (float*)d_out + OUT_ELEMS;

    float *p_tn, *p_sn, *p_q, *p_k, *p_v, *p_m, *p_z, *p_ao, *p_o1, *p_hid, *p_tmp, *p_sh;
    cudaGetSymbolAddress((void**)&p_tn, g_tn);
    cudaGetSymbolAddress((void**)&p_sn, g_sn);
    cudaGetSymbolAddress((void**)&p_q,  g_q);
    cudaGetSymbolAddress((void**)&p_k,  g_k);
    cudaGetSymbolAddress((void**)&p_v,  g_v);
    cudaGetSymbolAddress((void**)&p_m,  g_m);
    cudaGetSymbolAddress((void**)&p_z,  g_z);
    cudaGetSymbolAddress((void**)&p_ao, g_attnout);
    cudaGetSymbolAddress((void**)&p_o1, g_out1);
    cudaGetSymbolAddress((void**)&p_hid, g_hid);
    cudaGetSymbolAddress((void**)&p_tmp, g_tmp);
    cudaGetSymbolAddress((void**)&p_sh, g_shead);

    // 1. input LayerNorms + edge scalar
    ln_kernel<<<NROW_T, 128>>>(text, nullptr, tn_g, tn_b, p_tn, TD);
    ln_kernel<<<NROW_S, 128>>>(shape, nullptr, sn_g, sn_b, p_sn, SD);
    edge_scalar_kernel<<<1, 32>>>(edge_emb, ep_w, p_sh);

    // 2. projections (tensor-core)
    mma_gemm<64,64,2,2,1><<<dim3(TD/64, NROW_T/64), 128>>>(p_tn, Wq, bq, p_q, NROW_T, TD, TD, SS);
    mma_gemm<128,128,4,2,1><<<dim3(TD/128, NROW_S/128), 256>>>(p_sn, Wk, bk, p_k, NROW_S, TD, SD, PP);
    mma_gemm<128,128,4,2,1><<<dim3(TD/128, NROW_S/128), 256>>>(p_sn, Wv, bv, p_v, NROW_S, TD, SD, PP);

    // 3. attention
    attn_scores_kernel<<<dim3(SS/32, BB*HH), 256>>>(p_q, p_k, p_sh, ep_b, attn_buf, p_m, p_z);
    attn_pv_kernel<<<dim3(SS/64, BB*HH), 256>>>(p_v, p_m, p_z, attn_buf, p_ao);

    // 4. output proj + residual + LN
    mma_gemm<64,64,2,2,0><<<dim3(TD/64, NROW_T/64), 128>>>(p_ao, Wo, bo, p_tmp, NROW_T, TD, TD, 0);
    ln_kernel<<<NROW_T, 128>>>(text, p_tmp, on_g, on_b, p_o1, TD);

    // 5. FFN + residual + LN
    mma_gemm<64,64,2,2,2><<<dim3(FF/64, NROW_T/64), 128>>>(p_o1, W1, b1, p_hid, NROW_T, FF, TD, 0);
    mma_gemm<64,64,2,2,0><<<dim3(TD/64, NROW_T/64), 128>>>(p_hid, W2, b2, p_tmp, NROW_T, TD, FF, 0);
    ln_kernel<<<NROW_T, 128>>>(p_o1, p_tmp, fn_g, fn_b, out_final, TD);
}